// round 4
// baseline (speedup 1.0000x reference)
#include <cuda_runtime.h>
#include <cstdint>

// Unpool (2x2 max-unpool inverse scatter), done as a single-pass gather/expand.
// Input:  val  fp32  [B,H,W,C]      = [16,64,64,128]
//         mask int32 [B,H,W,C]  flat index (batch-offset included) into output
//         (JAX default x64-disabled -> the "int64" mask is materialized int32;
//          max index 33,554,432 fits easily. Round-1 int64 reads faulted,
//          confirming the buffer is 32 MB.)
// Output: out  fp32  [B,2H,2W,C]    = [16,128,128,128]
//
// For input cell (b,h,w,c), the mask can only point at one of the 4 positions
// (2h+dh, 2w+dw), dh,dw in {0,1}. So delta = mask - base is in
// {0, C, W2*C, W2*C + C}. Each thread handles 4 channels (float4) of one
// pooled cell and writes the four output quadrant vectors directly — every
// output byte written exactly once, no memset pass, no atomics.

namespace {
constexpr int B  = 16;
constexpr int H  = 64;
constexpr int W  = 64;
constexpr int C  = 128;
constexpr int H2 = H * 2;
constexpr int W2 = W * 2;
constexpr int C4 = C / 4;                        // 32 float4 per channel row
constexpr int NTHREADS_TOTAL = B * H * W * C4;   // 2,097,152 = 2^21
constexpr int TPB = 256;

// deltas (in fp32 elements) for the 4 quadrant positions
constexpr int D01 = C;            // (dh=0, dw=1)
constexpr int D10 = W2 * C;       // (dh=1, dw=0)
constexpr int D11 = W2 * C + C;   // (dh=1, dw=1)
}

__global__ void __launch_bounds__(TPB)
unpool_expand_kernel(const float4* __restrict__ val4,
                     const int4*   __restrict__ mask4,
                     float4*       __restrict__ out4) {
    const int tid = blockIdx.x * TPB + threadIdx.x;

    // tid bits: [0:5)=c4, [5:11)=w, [11:17)=h, [17:21)=b
    const int c4 = tid & (C4 - 1);
    const int w  = (tid >> 5)  & (W - 1);
    const int h  = (tid >> 11) & (H - 1);
    const int b  = tid >> 17;

    // val load: 16B per thread, warp-contiguous 512B
    const float4 v = val4[tid];
    // mask load: 16B per thread, warp-contiguous 512B
    const int4   m = mask4[tid];

    // shared cell base: float4 row index of output (b, 2h, 2w)
    const int cell = (b * H2 + 2 * h) * W2 + 2 * w;

    // flat output element index of (b, 2h, 2w, c4*4)
    const int base = cell * C + (c4 << 2);

    // per-lane delta: which quadrant this element was pooled from
    const int d0 = m.x - base;
    const int d1 = m.y - (base + 1);
    const int d2 = m.z - (base + 2);
    const int d3 = m.w - (base + 3);

    float4 o00, o01, o10, o11;
    o00.x = (d0 == 0)   ? v.x : 0.0f;
    o00.y = (d1 == 0)   ? v.y : 0.0f;
    o00.z = (d2 == 0)   ? v.z : 0.0f;
    o00.w = (d3 == 0)   ? v.w : 0.0f;

    o01.x = (d0 == D01) ? v.x : 0.0f;
    o01.y = (d1 == D01) ? v.y : 0.0f;
    o01.z = (d2 == D01) ? v.z : 0.0f;
    o01.w = (d3 == D01) ? v.w : 0.0f;

    o10.x = (d0 == D10) ? v.x : 0.0f;
    o10.y = (d1 == D10) ? v.y : 0.0f;
    o10.z = (d2 == D10) ? v.z : 0.0f;
    o10.w = (d3 == D10) ? v.w : 0.0f;

    o11.x = (d0 == D11) ? v.x : 0.0f;
    o11.y = (d1 == D11) ? v.y : 0.0f;
    o11.z = (d2 == D11) ? v.z : 0.0f;
    o11.w = (d3 == D11) ? v.w : 0.0f;

    // output float4 index of (b, 2h, 2w, c4)
    const int obase = cell * C4 + c4;

    // four coalesced 512B-per-warp stores (one per quadrant position)
    out4[obase]                 = o00;   // (2h,   2w  )
    out4[obase + C4]            = o01;   // (2h,   2w+1)
    out4[obase + W2 * C4]       = o10;   // (2h+1, 2w  )
    out4[obase + W2 * C4 + C4]  = o11;   // (2h+1, 2w+1)
}

extern "C" void kernel_launch(void* const* d_in, const int* in_sizes, int n_in,
                              void* d_out, int out_size) {
    const float4* val4  = (const float4*)d_in[0];
    const int4*   mask4 = (const int4*)d_in[1];
    float4*       out4  = (float4*)d_out;

    const int nblocks = NTHREADS_TOTAL / TPB;  // 8192
    unpool_expand_kernel<<<nblocks, TPB>>>(val4, mask4, out4);
}